// round 1
// baseline (speedup 1.0000x reference)
#include <cuda_runtime.h>
#include <math.h>

#define BB 2
#define CC 5
#define TT 8
#define HH 256
#define WW 512
#define NPIX (TT*HH*WW)        // 1048576 = 2^20
#define KM 8
#define NSEG (BB*KM)           // 16
#define NB 32768               // histogram bins over e in [0,2]

// ---------------- static device scratch (no runtime allocation) ----------------
__device__ unsigned int d_hist[NSEG * 2 * NB];   // [seg][label][bin], 4MB, L2-resident
__device__ int    d_cnt[NSEG];
__device__ int    d_sit[NSEG], d_siy[NSEG], d_six[NSEG];  // exact integer index sums
__device__ double d_ssig[NSEG], d_ssig2[NSEG];
__device__ double d_seedbg[BB], d_seedfg[BB];
__device__ float  d_ctr0[NSEG], d_ctr1[NSEG], d_ctr2[NSEG];
__device__ float  d_c2[NSEG];
__device__ float  d_sexp[NSEG];
__device__ float  d_var[NSEG];
__device__ float  d_pres[NSEG];
__device__ double d_inst[NSEG];

// linspace steps (match jnp.linspace(0,0.1,32)[:8] etc.)
#define DT_STEP ((float)(0.1 / 31.0))
#define DY_STEP ((float)(1.6 / 799.0))
#define DX_STEP ((float)(4.16 / 1999.0))

// ---------------- zero scratch ----------------
__global__ void k_zero() {
    int i = blockIdx.x * blockDim.x + threadIdx.x;
    int stride = gridDim.x * blockDim.x;
    int n = NSEG * 2 * NB;
    for (int j = i; j < n; j += stride) d_hist[j] = 0u;
    if (i < NSEG) {
        d_cnt[i] = 0; d_sit[i] = 0; d_siy[i] = 0; d_six[i] = 0;
        d_ssig[i] = 0.0; d_ssig2[i] = 0.0; d_inst[i] = 0.0;
    }
    if (i < BB) { d_seedbg[i] = 0.0; d_seedfg[i] = 0.0; }
}

// ---------------- K1: per-(b,k) masked statistics ----------------
#define PIX1 8
__global__ void k_stats(const float* __restrict__ pred, const int* __restrict__ inst) {
    __shared__ int s_cnt[KM], s_it[KM], s_iy[KM], s_ix[KM];
    __shared__ double s_sg[KM], s_sg2[KM];
    int b = blockIdx.y;
    int tid = threadIdx.x;
    if (tid < KM) { s_cnt[tid]=0; s_it[tid]=0; s_iy[tid]=0; s_ix[tid]=0; s_sg[tid]=0.0; s_sg2[tid]=0.0; }
    __syncthreads();

    const float* sig = pred + ((size_t)b * CC + 3) * NPIX;
    const int*   ib  = inst + (size_t)b * NPIX;
    int base = blockIdx.x * (blockDim.x * PIX1);
    #pragma unroll
    for (int r = 0; r < PIX1; r++) {
        int p = base + r * blockDim.x + tid;
        int v = ib[p];
        if (v > 0) {
            int k = v - 1;
            float s = sig[p];
            atomicAdd(&s_cnt[k], 1);
            atomicAdd(&s_it[k], p >> 17);
            atomicAdd(&s_iy[k], (p >> 9) & 255);
            atomicAdd(&s_ix[k], p & 511);
            atomicAdd(&s_sg[k], (double)s);
            atomicAdd(&s_sg2[k], (double)s * (double)s);
        }
    }
    __syncthreads();
    if (tid < KM) {
        int seg = b * KM + tid;
        atomicAdd(&d_cnt[seg], s_cnt[tid]);
        atomicAdd(&d_sit[seg], s_it[tid]);
        atomicAdd(&d_siy[seg], s_iy[tid]);
        atomicAdd(&d_six[seg], s_ix[tid]);
        atomicAdd(&d_ssig[seg], s_sg[tid]);
        atomicAdd(&d_ssig2[seg], s_sg2[tid]);
    }
}

// ---------------- K2: finalize centers / s_exp / var ----------------
__global__ void k_final() {
    int s = threadIdx.x;
    if (s >= NSEG) return;
    double cnt  = (double)d_cnt[s];
    double safe = cnt > 0.0 ? cnt : 1.0;
    double ct = (0.1 / 31.0)   * (double)d_sit[s] / safe;
    double cy = (1.6 / 799.0)  * (double)d_siy[s] / safe;
    double cx = (4.16 / 1999.0)* (double)d_six[s] / safe;
    double sm = d_ssig[s]  / safe;
    double s2 = d_ssig2[s] / safe;
    d_ctr0[s] = (float)ct; d_ctr1[s] = (float)cy; d_ctr2[s] = (float)cx;
    d_c2[s]   = (float)(ct*ct + cy*cy + cx*cx);
    d_sexp[s] = (float)exp(10.0 * sm);
    d_var[s]  = (float)(s2 - sm * sm);   // sig2 - 2*s_sg*s_mean + s_sg^2 with s_sg == s_mean
    d_pres[s] = (cnt > 0.0) ? 1.0f : 0.0f;
}

// ---------------- K3: main pass — dist, histogram, seed terms ----------------
__inline__ __device__ double warpSumD(double v) {
    #pragma unroll
    for (int o = 16; o > 0; o >>= 1) v += __shfl_down_sync(0xffffffffu, v, o);
    return v;
}

#define PIX3 4
__global__ void k_main(const float* __restrict__ pred, const int* __restrict__ inst) {
    __shared__ float sc0[KM], sc1[KM], sc2[KM], sc3[KM], sse[KM];
    int b = blockIdx.y;
    int tid = threadIdx.x;
    if (tid < KM) {
        int seg = b * KM + tid;
        sc0[tid] = d_ctr0[seg]; sc1[tid] = d_ctr1[seg]; sc2[tid] = d_ctr2[seg];
        sc3[tid] = d_c2[seg];   sse[tid] = d_sexp[seg];
    }
    __syncthreads();

    const float* p0 = pred + (size_t)b * CC * NPIX;
    const int*   ib = inst + (size_t)b * NPIX;
    unsigned int* histb = d_hist + (size_t)b * KM * 2 * NB;

    double fg = 0.0, bg = 0.0;
    int base = blockIdx.x * (blockDim.x * PIX3);
    #pragma unroll
    for (int r = 0; r < PIX3; r++) {
        int p = base + r * blockDim.x + tid;
        float a0 = tanhf(p0[p]);
        float a1 = tanhf(p0[NPIX + p]);
        float a2 = tanhf(p0[2 * NPIX + p]);
        float sv = p0[4 * NPIX + p];
        float seed = 1.0f / (1.0f + __expf(-sv));
        int t = p >> 17, y = (p >> 9) & 255, x = p & 511;
        float e0 = a0 + (float)t * DT_STEP;
        float e1 = a1 + (float)y * DY_STEP;
        float e2 = a2 + (float)x * DX_STEP;
        float ee = e0*e0 + e1*e1 + e2*e2;
        int iv = ib[p];
        if (iv == 0) bg += (double)(seed * seed);

        #pragma unroll
        for (int k = 0; k < KM; k++) {
            float ec = e0 * sc0[k] + e1 * sc1[k] + e2 * sc2[k];
            float sq = ee - 2.0f * ec + sc3[k];
            float dist = __expf(-sse[k] * sq);
            int lab = (iv == k + 1) ? 1 : 0;
            if (lab) { float df = seed - dist; fg += (double)(df * df); }
            float e = lab ? (2.0f - 2.0f * dist) : (2.0f * dist);
            e = fmaxf(e, 0.0f);
            int bin = (int)(e * (float)(NB / 2));
            bin = min(bin, NB - 1);
            // bin 0 elements never enter any suffix j>=1: skip (kills hottest atomic)
            int do_add = (bin > 0);
            unsigned active = __ballot_sync(0xffffffffu, do_add);
            if (do_add) {
                unsigned key = (unsigned)bin | ((unsigned)lab << 20);
                unsigned peers = __match_any_sync(active, key);
                int leader = __ffs(peers) - 1;
                if ((tid & 31) == leader) {
                    atomicAdd(&histb[((size_t)k * 2 + lab) * NB + bin],
                              (unsigned)__popc(peers));
                }
            }
        }
    }

    // block reduce seed terms
    fg = warpSumD(fg); bg = warpSumD(bg);
    __shared__ double wfg[8], wbg[8];
    int wid = tid >> 5, lid = tid & 31;
    if (lid == 0) { wfg[wid] = fg; wbg[wid] = bg; }
    __syncthreads();
    if (wid == 0) {
        double f2 = (lid < (blockDim.x >> 5)) ? wfg[lid] : 0.0;
        double b2 = (lid < (blockDim.x >> 5)) ? wbg[lid] : 0.0;
        f2 = warpSumD(f2); b2 = warpSumD(b2);
        if (lid == 0) { atomicAdd(&d_seedfg[b], f2); atomicAdd(&d_seedbg[b], b2); }
    }
}

// ---------------- K4: Lovász via histogram suffix scan ----------------
// S = w * sum_{j=1}^{NB-1} (p_j + n_j) / (P + n_j),  p_j/n_j = suffix counts from bin j
__global__ void k_lovasz() {
    int seg = blockIdx.x;
    int tid = threadIdx.x;
    int P = d_cnt[seg];
    if (P == 0) { if (tid == 0) d_inst[seg] = 0.0; return; }
    const unsigned* hn = d_hist + (size_t)(seg * 2 + 0) * NB;
    const unsigned* hp = d_hist + (size_t)(seg * 2 + 1) * NB;
    const int CH = NB / 256;  // 128 bins per thread
    int lo = tid * CH, hi = lo + CH;
    int cp = 0, cn = 0;
    for (int j = lo; j < hi; j++) { cp += (int)hp[j]; cn += (int)hn[j]; }
    __shared__ int sp[256], sn[256];
    sp[tid] = cp; sn[tid] = cn;
    __syncthreads();
    int supP = 0, supN = 0;
    for (int u = tid + 1; u < 256; u++) { supP += sp[u]; supN += sn[u]; }
    double jsum = 0.0;
    int p = supP, n = supN;
    for (int j = hi - 1; j >= lo; j--) {
        p += (int)hp[j]; n += (int)hn[j];
        if (j >= 1) {
            int tot = p + n;
            if (tot > 0) jsum += (double)tot / (double)(P + n);
        }
    }
    jsum = warpSumD(jsum);
    __shared__ double wj[8];
    int wid = tid >> 5, lid = tid & 31;
    if (lid == 0) wj[wid] = jsum;
    __syncthreads();
    if (wid == 0) {
        double v = (lid < 8) ? wj[lid] : 0.0;
        v = warpSumD(v);
        if (lid == 0) d_inst[seg] = v * (2.0 / (double)NB);
    }
}

// ---------------- K5: combine into scalar ----------------
__global__ void k_out(float* out) {
    if (threadIdx.x == 0 && blockIdx.x == 0) {
        double tot = 0.0;
        for (int b = 0; b < BB; b++) {
            double obj = 0.0, il = 0.0, vl = 0.0;
            for (int k = 0; k < KM; k++) {
                int s = b * KM + k;
                double pr = (double)d_pres[s];
                obj += pr;
                il += d_inst[s] * pr;
                vl += (double)d_var[s] * pr;
            }
            double so = obj > 0.0 ? obj : 1.0;
            double seedl = (d_seedbg[b] + d_seedfg[b]) / (double)(HH * WW);
            tot += 1.0 * (il / so) + 10.0 * (vl / so) + 1.0 * seedl;
        }
        out[0] = (float)(tot / (double)BB);
    }
}

// ---------------- launch ----------------
extern "C" void kernel_launch(void* const* d_in, const int* in_sizes, int n_in,
                              void* d_out, int out_size) {
    const float* pred = (const float*)d_in[0];
    const int*   inst = (const int*)d_in[1];
    (void)in_sizes; (void)n_in; (void)out_size;

    k_zero<<<2048, 256>>>();

    dim3 g1(NPIX / (256 * PIX1), BB);
    k_stats<<<g1, 256>>>(pred, inst);

    k_final<<<1, 32>>>();

    dim3 g3(NPIX / (256 * PIX3), BB);
    k_main<<<g3, 256>>>(pred, inst);

    k_lovasz<<<NSEG, 256>>>();

    k_out<<<1, 1>>>((float*)d_out);
}

// round 2
// speedup vs baseline: 2.5978x; 2.5978x over previous
#include <cuda_runtime.h>
#include <math.h>

#define BB 2
#define TT 8
#define HH 256
#define WW 512
#define NPIX (TT*HH*WW)        // 1048576
#define KM 8
#define NSEG (BB*KM)           // 16
#define NB 4096                // histogram bins over e in [0,2]; w = 2/NB
#define CHUNKS 222             // blocks per batch in k_main (one wave: 2*222=444 = 148 SMs * 3)
#define NSLOT (BB*CHUNKS)
#define HWORDS (KM*NB/2)       // packed u16 words per block hist = 16384
#define MAIN_ITERS ((NPIX + CHUNKS*256 - 1)/(CHUNKS*256))   // 19

// ---------------- static device scratch ----------------
__device__ unsigned short d_bhist[(size_t)NSLOT * KM * NB]; // per-block private hists (~29MB)
__device__ unsigned int d_histneg[NSEG * NB];               // summed negative hist
__device__ unsigned int d_histpos[NSEG * NB];               // positive hist (global atomics)
__device__ int    d_cnt[NSEG];
__device__ int    d_sit[NSEG], d_siy[NSEG], d_six[NSEG];
__device__ double d_ssig[NSEG], d_ssig2[NSEG];
__device__ double d_seedbg[BB], d_seedfg[BB];
__device__ float  d_ctr0[NSEG], d_ctr1[NSEG], d_ctr2[NSEG];
__device__ float  d_c2[NSEG], d_sexp[NSEG], d_var[NSEG], d_pres[NSEG];
__device__ double d_inst[NSEG];

#define DT_STEP ((float)(0.1 / 31.0))
#define DY_STEP ((float)(1.6 / 799.0))
#define DX_STEP ((float)(4.16 / 1999.0))

// ---------------- zero ----------------
__global__ void k_zero() {
    int i = blockIdx.x * blockDim.x + threadIdx.x;
    int stride = gridDim.x * blockDim.x;
    for (int j = i; j < NSEG * NB; j += stride) d_histpos[j] = 0u;
    if (i < NSEG) {
        d_cnt[i] = 0; d_sit[i] = 0; d_siy[i] = 0; d_six[i] = 0;
        d_ssig[i] = 0.0; d_ssig2[i] = 0.0; d_inst[i] = 0.0;
    }
    if (i < BB) { d_seedbg[i] = 0.0; d_seedfg[i] = 0.0; }
}

// ---------------- K1: masked statistics (atomic-free inner loop) ----------------
__global__ void k_stats(const float* __restrict__ pred, const int* __restrict__ inst) {
    int b = blockIdx.y;
    const float* sig = pred + ((size_t)b * 5 + 3) * NPIX;
    const int*   ib  = inst + (size_t)b * NPIX;

    int   cnt[KM], it[KM], iy[KM], ix[KM];
    float s1[KM], s2[KM];
    #pragma unroll
    for (int k = 0; k < KM; k++) { cnt[k]=0; it[k]=0; iy[k]=0; ix[k]=0; s1[k]=0.f; s2[k]=0.f; }

    int base = blockIdx.x * 256 + threadIdx.x;   // grid.x = 64
    #pragma unroll 4
    for (int i = 0; i < 64; i++) {
        int p = base + i * (64 * 256);
        int v = ib[p];
        float s = sig[p];
        int t = p >> 17, y = (p >> 9) & 255, x = p & 511;
        float ss = s * s;
        #pragma unroll
        for (int k = 0; k < KM; k++) {
            if (v == k + 1) { cnt[k]++; it[k]+=t; iy[k]+=y; ix[k]+=x; s1[k]+=s; s2[k]+=ss; }
        }
    }
    int lane = threadIdx.x & 31;
    #pragma unroll
    for (int k = 0; k < KM; k++) {
        #pragma unroll
        for (int o = 16; o > 0; o >>= 1) {
            cnt[k] += __shfl_down_sync(0xffffffffu, cnt[k], o);
            it[k]  += __shfl_down_sync(0xffffffffu, it[k],  o);
            iy[k]  += __shfl_down_sync(0xffffffffu, iy[k],  o);
            ix[k]  += __shfl_down_sync(0xffffffffu, ix[k],  o);
            s1[k]  += __shfl_down_sync(0xffffffffu, s1[k],  o);
            s2[k]  += __shfl_down_sync(0xffffffffu, s2[k],  o);
        }
        if (lane == 0) {
            int seg = b * KM + k;
            atomicAdd(&d_cnt[seg], cnt[k]);
            atomicAdd(&d_sit[seg], it[k]);
            atomicAdd(&d_siy[seg], iy[k]);
            atomicAdd(&d_six[seg], ix[k]);
            atomicAdd(&d_ssig[seg],  (double)s1[k]);
            atomicAdd(&d_ssig2[seg], (double)s2[k]);
        }
    }
}

// ---------------- K2: finalize ----------------
__global__ void k_final() {
    int s = threadIdx.x;
    if (s >= NSEG) return;
    double cnt  = (double)d_cnt[s];
    double safe = cnt > 0.0 ? cnt : 1.0;
    double ct = (0.1 / 31.0)    * (double)d_sit[s] / safe;
    double cy = (1.6 / 799.0)   * (double)d_siy[s] / safe;
    double cx = (4.16 / 1999.0) * (double)d_six[s] / safe;
    double sm = d_ssig[s]  / safe;
    double s2 = d_ssig2[s] / safe;
    d_ctr0[s] = (float)ct; d_ctr1[s] = (float)cy; d_ctr2[s] = (float)cx;
    d_c2[s]   = (float)(ct*ct + cy*cy + cx*cx);
    d_sexp[s] = (float)exp(10.0 * sm);
    d_var[s]  = (float)(s2 - sm * sm);
    d_pres[s] = (cnt > 0.0) ? 1.0f : 0.0f;
}

__inline__ __device__ double warpSumD(double v) {
    #pragma unroll
    for (int o = 16; o > 0; o >>= 1) v += __shfl_down_sync(0xffffffffu, v, o);
    return v;
}
__inline__ __device__ float warpSumF(float v) {
    #pragma unroll
    for (int o = 16; o > 0; o >>= 1) v += __shfl_down_sync(0xffffffffu, v, o);
    return v;
}

// ---------------- K3: main pass with smem private histogram ----------------
__global__ void __launch_bounds__(256, 3)
k_main(const float* __restrict__ pred, const int* __restrict__ inst) {
    extern __shared__ unsigned int sh[];   // HWORDS words = 64KB
    int b = blockIdx.y;
    int tid = threadIdx.x;
    for (int i = tid; i < HWORDS; i += 256) sh[i] = 0u;

    float c0[KM], c1[KM], c2[KM], cc[KM], se[KM];
    #pragma unroll
    for (int k = 0; k < KM; k++) {
        int s = b * KM + k;
        c0[k]=d_ctr0[s]; c1[k]=d_ctr1[s]; c2[k]=d_ctr2[s]; cc[k]=d_c2[s]; se[k]=d_sexp[s];
    }
    __syncthreads();

    const float* p0 = pred + (size_t)b * 5 * NPIX;
    const int*   ib = inst + (size_t)b * NPIX;
    double fg = 0.0, bg = 0.0;
    int base = blockIdx.x * 256 + tid;

    for (int i = 0; i < MAIN_ITERS; i++) {
        int p = base + i * (CHUNKS * 256);
        if (p < NPIX) {
            float f0 = p0[p], f1 = p0[NPIX + p], f2 = p0[2 * NPIX + p], sv = p0[4 * NPIX + p];
            // accurate-enough tanh via expf: tanh(x) = 1 - 2/(exp(2x)+1)
            float a0 = 1.0f - 2.0f / (__expf(2.0f * f0) + 1.0f);
            float a1 = 1.0f - 2.0f / (__expf(2.0f * f1) + 1.0f);
            float a2 = 1.0f - 2.0f / (__expf(2.0f * f2) + 1.0f);
            int t = p >> 17, y = (p >> 9) & 255, x = p & 511;
            float e0 = a0 + (float)t * DT_STEP;
            float e1 = a1 + (float)y * DY_STEP;
            float e2 = a2 + (float)x * DX_STEP;
            float ee = e0*e0 + e1*e1 + e2*e2;
            float seed = 1.0f / (1.0f + __expf(-sv));
            int iv = ib[p];
            if (iv == 0) bg += (double)(seed * seed);

            #pragma unroll
            for (int k = 0; k < KM; k++) {
                float sq = ee - 2.0f * (e0*c0[k] + e1*c1[k] + e2*c2[k]) + cc[k];
                float dist = __expf(-se[k] * sq);
                if (iv == k + 1) {
                    float df = seed - dist; fg += (double)(df * df);
                    int bin = (int)((1.0f - dist) * (float)NB);
                    bin = min(bin, NB - 1);
                    if (bin > 0) atomicAdd(&d_histpos[(b * KM + k) * NB + bin], 1u);
                } else {
                    int bin = (int)(dist * (float)NB);
                    bin = min(bin, NB - 1);
                    if (bin > 0)
                        atomicAdd(&sh[k * (NB / 2) + (bin >> 1)], 1u << ((bin & 1) << 4));
                }
            }
        }
    }
    __syncthreads();

    // flush private hist (plain stores, no atomics)
    unsigned int* dst = (unsigned int*)d_bhist + (size_t)(b * CHUNKS + blockIdx.x) * HWORDS;
    for (int i = tid; i < HWORDS; i += 256) dst[i] = sh[i];

    // reduce seed terms
    fg = warpSumD(fg); bg = warpSumD(bg);
    __shared__ double wfg[8], wbg[8];
    int wid = tid >> 5, lid = tid & 31;
    if (lid == 0) { wfg[wid] = fg; wbg[wid] = bg; }
    __syncthreads();
    if (wid == 0) {
        double f2s = (lid < 8) ? wfg[lid] : 0.0;
        double b2s = (lid < 8) ? wbg[lid] : 0.0;
        f2s = warpSumD(f2s); b2s = warpSumD(b2s);
        if (lid == 0) { atomicAdd(&d_seedfg[b], f2s); atomicAdd(&d_seedbg[b], b2s); }
    }
}

// ---------------- K3b: sum per-block hists (plain loads/stores) ----------------
__global__ void k_reduce() {
    int id = blockIdx.x * 256 + threadIdx.x;     // 0 .. NSEG*NB/2-1 = 32767
    int seg = id >> 11;                           // NB/2 = 2048 words per seg
    int w   = id & 2047;
    int b = seg >> 3, k = seg & 7;
    const unsigned int* src = (const unsigned int*)d_bhist;
    size_t off = (size_t)(b * CHUNKS) * HWORDS + (size_t)k * (NB / 2) + w;
    unsigned int lo = 0, hi = 0;
    #pragma unroll 4
    for (int c = 0; c < CHUNKS; c++) {
        unsigned int v = src[off + (size_t)c * HWORDS];
        lo += v & 0xffffu; hi += v >> 16;
    }
    d_histneg[seg * NB + 2 * w]     = lo;
    d_histneg[seg * NB + 2 * w + 1] = hi;
}

// ---------------- K4: Lovász via suffix scan (trapezoid) ----------------
__global__ void k_lovasz() {
    int seg = blockIdx.x;
    int tid = threadIdx.x;
    int Pi = d_cnt[seg];
    if (Pi == 0) { if (tid == 0) d_inst[seg] = 0.0; return; }
    float P = (float)Pi;
    const unsigned* hn = d_histneg + seg * NB;
    const unsigned* hp = d_histpos + seg * NB;
    const int CH = NB / 256;   // 16 bins per thread
    int lo = tid * CH;
    int cp = 0, cn = 0;
    #pragma unroll
    for (int j = 0; j < CH; j++) { cp += (int)hp[lo + j]; cn += (int)hn[lo + j]; }
    __shared__ int sp[256], sn[256];
    sp[tid] = cp; sn[tid] = cn;
    __syncthreads();
    int supP = 0, supN = 0;
    for (int u = tid + 1; u < 256; u++) { supP += sp[u]; supN += sn[u]; }
    float jsum = 0.0f;
    int p = supP, n = supN;
    for (int j = lo + CH - 1; j >= lo; j--) {
        p += (int)hp[j]; n += (int)hn[j];
        if (j >= 1) jsum += (float)(p + n) / (P + (float)n);
    }
    jsum = warpSumF(jsum);
    __shared__ float wj[8];
    int wid = tid >> 5, lid = tid & 31;
    if (lid == 0) wj[wid] = jsum;
    __syncthreads();
    if (wid == 0) {
        float v = (lid < 8) ? wj[lid] : 0.0f;
        v = warpSumF(v);
        // trapezoid = lower Riemann sum + w/2  (J monotone, J(0)=1, J(end)=0)
        if (lid == 0) d_inst[seg] = ((double)v + 0.5) * (2.0 / (double)NB);
    }
}

// ---------------- K5: combine ----------------
__global__ void k_out(float* out) {
    if (threadIdx.x == 0 && blockIdx.x == 0) {
        double tot = 0.0;
        for (int b = 0; b < BB; b++) {
            double obj = 0.0, il = 0.0, vl = 0.0;
            for (int k = 0; k < KM; k++) {
                int s = b * KM + k;
                double pr = (double)d_pres[s];
                obj += pr;
                il += d_inst[s] * pr;
                vl += (double)d_var[s] * pr;
            }
            double so = obj > 0.0 ? obj : 1.0;
            double seedl = (d_seedbg[b] + d_seedfg[b]) / (double)(HH * WW);
            tot += 1.0 * (il / so) + 10.0 * (vl / so) + 1.0 * seedl;
        }
        out[0] = (float)(tot / (double)BB);
    }
}

// ---------------- launch ----------------
extern "C" void kernel_launch(void* const* d_in, const int* in_sizes, int n_in,
                              void* d_out, int out_size) {
    const float* pred = (const float*)d_in[0];
    const int*   inst = (const int*)d_in[1];
    (void)in_sizes; (void)n_in; (void)out_size;

    static bool attr_done = false;
    if (!attr_done) {
        cudaFuncSetAttribute(k_main, cudaFuncAttributeMaxDynamicSharedMemorySize,
                             HWORDS * sizeof(unsigned int));
        attr_done = true;
    }

    k_zero<<<256, 256>>>();

    dim3 g1(64, BB);
    k_stats<<<g1, 256>>>(pred, inst);

    k_final<<<1, 32>>>();

    dim3 g3(CHUNKS, BB);
    k_main<<<g3, 256, HWORDS * sizeof(unsigned int)>>>(pred, inst);

    k_reduce<<<(NSEG * NB / 2) / 256, 256>>>();

    k_lovasz<<<NSEG, 256>>>();

    k_out<<<1, 1>>>((float*)d_out);
}